// round 2
// baseline (speedup 1.0000x reference)
#include <cuda_runtime.h>
#include <math.h>

#define NN 50000
#define EE 800000
#define DD 256
#define HH 8
#define HDIM 32
#define FF 1024
#define SCALE 0.0625f   // 256^-0.5
#define EPSL 1e-5f

// ---------------- scratch (device globals; no allocation allowed) ----------
__device__ float g_qkv[(size_t)NN * 768];     // per node: H heads x (q|k|v) 96 floats
__device__ float g_attn[(size_t)NN * DD];     // attention output
__device__ float g_x1[(size_t)NN * DD];       // after first LN
__device__ float g_hidden[(size_t)NN * FF];   // relu(x1@w1+b1)
__device__ float g_ffn[(size_t)NN * DD];      // hidden@w2+b2
__device__ int   g_deg[NN];
__device__ int   g_off[NN + 1];
__device__ int   g_cursor[NN];
__device__ int   g_nbr[EE];

// ---------------- CSR construction -----------------------------------------
__global__ void zero_counts_kernel() {
    int i = blockIdx.x * blockDim.x + threadIdx.x;
    if (i < NN) { g_deg[i] = 0; g_cursor[i] = 0; }
}

__global__ void hist_kernel(const int* __restrict__ rows) {
    int e = blockIdx.x * blockDim.x + threadIdx.x;
    if (e < EE) atomicAdd(&g_deg[rows[e]], 1);
}

__global__ void scan_kernel() {
    __shared__ int sh[1024];
    __shared__ int carry;
    int t = threadIdx.x;
    if (t == 0) { carry = 0; g_off[0] = 0; }
    __syncthreads();
    for (int base = 0; base < NN; base += 1024) {
        int i = base + t;
        int v = (i < NN) ? g_deg[i] : 0;
        sh[t] = v;
        __syncthreads();
        #pragma unroll
        for (int d = 1; d < 1024; d <<= 1) {
            int tv = (t >= d) ? sh[t - d] : 0;
            __syncthreads();
            sh[t] += tv;
            __syncthreads();
        }
        if (i < NN) g_off[i + 1] = carry + sh[t];
        __syncthreads();
        if (t == 0) carry += sh[1023];
        __syncthreads();
    }
}

__global__ void scatter_kernel(const int* __restrict__ rows, const int* __restrict__ cols) {
    int e = blockIdx.x * blockDim.x + threadIdx.x;
    if (e < EE) {
        int r = rows[e];
        int pos = g_off[r] + atomicAdd(&g_cursor[r], 1);
        g_nbr[pos] = cols[e];
    }
}

// ---------------- SGEMM: C[M,N] = A[M,K] @ B[K,N] + bias, optional ReLU ----
// 128x128 block tile, 8 k-step, 256 threads, 8x8 per-thread register tile.
#define BM 128
#define BN 128
#define BK 8
#define TM 8
#define TN 8

template <bool RELU>
__global__ __launch_bounds__(256) void sgemm_kernel(
    const float* __restrict__ A, const float* __restrict__ B,
    const float* __restrict__ bias, float* __restrict__ C,
    int M, int N, int K)
{
    __shared__ float As[BK][BM];
    __shared__ float Bs[BK][BN];

    int tid = threadIdx.x;
    int brow = blockIdx.y * BM;
    int bcol = blockIdx.x * BN;

    int aRow  = tid >> 1;          // 0..127
    int aCol4 = (tid & 1) * 4;     // 0 or 4
    int bRow  = tid >> 5;          // 0..7
    int bCol4 = (tid & 31) * 4;    // 0..124

    int ty = tid >> 4;             // 0..15
    int tx = tid & 15;             // 0..15

    float acc[TM][TN];
    #pragma unroll
    for (int i = 0; i < TM; i++)
        #pragma unroll
        for (int j = 0; j < TN; j++) acc[i][j] = 0.f;

    for (int k0 = 0; k0 < K; k0 += BK) {
        // load A tile (transposed into As)
        int gr = brow + aRow;
        float4 a4;
        if (gr < M)
            a4 = *reinterpret_cast<const float4*>(&A[(size_t)gr * K + k0 + aCol4]);
        else
            a4 = make_float4(0.f, 0.f, 0.f, 0.f);
        As[aCol4 + 0][aRow] = a4.x;
        As[aCol4 + 1][aRow] = a4.y;
        As[aCol4 + 2][aRow] = a4.z;
        As[aCol4 + 3][aRow] = a4.w;
        // load B tile
        float4 b4 = *reinterpret_cast<const float4*>(&B[(size_t)(k0 + bRow) * N + bcol + bCol4]);
        *reinterpret_cast<float4*>(&Bs[bRow][bCol4]) = b4;
        __syncthreads();

        #pragma unroll
        for (int k = 0; k < BK; k++) {
            float ra[TM], rb[TN];
            float4 t0 = *reinterpret_cast<const float4*>(&As[k][ty * TM]);
            float4 t1 = *reinterpret_cast<const float4*>(&As[k][ty * TM + 4]);
            ra[0] = t0.x; ra[1] = t0.y; ra[2] = t0.z; ra[3] = t0.w;
            ra[4] = t1.x; ra[5] = t1.y; ra[6] = t1.z; ra[7] = t1.w;
            float4 u0 = *reinterpret_cast<const float4*>(&Bs[k][tx * TN]);
            float4 u1 = *reinterpret_cast<const float4*>(&Bs[k][tx * TN + 4]);
            rb[0] = u0.x; rb[1] = u0.y; rb[2] = u0.z; rb[3] = u0.w;
            rb[4] = u1.x; rb[5] = u1.y; rb[6] = u1.z; rb[7] = u1.w;
            #pragma unroll
            for (int i = 0; i < TM; i++)
                #pragma unroll
                for (int j = 0; j < TN; j++)
                    acc[i][j] = fmaf(ra[i], rb[j], acc[i][j]);
        }
        __syncthreads();
    }

    #pragma unroll
    for (int i = 0; i < TM; i++) {
        int gr = brow + ty * TM + i;
        if (gr < M) {
            #pragma unroll
            for (int j = 0; j < TN; j += 4) {
                int gc = bcol + tx * TN + j;
                float4 bv = *reinterpret_cast<const float4*>(&bias[gc]);
                float4 o;
                o.x = acc[i][j + 0] + bv.x;
                o.y = acc[i][j + 1] + bv.y;
                o.z = acc[i][j + 2] + bv.z;
                o.w = acc[i][j + 3] + bv.w;
                if (RELU) {
                    o.x = fmaxf(o.x, 0.f); o.y = fmaxf(o.y, 0.f);
                    o.z = fmaxf(o.z, 0.f); o.w = fmaxf(o.w, 0.f);
                }
                *reinterpret_cast<float4*>(&C[(size_t)gr * N + gc]) = o;
            }
        }
    }
}

// ---------------- fused per-node attention (online softmax) ----------------
// One block per node (256 threads = 8 warps); warp h handles head h;
// lane d holds dimension d of that head.
// qkv layout per node (row of 768): head h occupies [h*96, h*96+96):
//   q = [h*96, h*96+32), k = [h*96+32, h*96+64), v = [h*96+64, h*96+96)
#define CHUNK 256

__global__ __launch_bounds__(256) void attn_kernel() {
    int r = blockIdx.x;
    int tid = threadIdx.x;
    int warp = tid >> 5;
    int lane = tid & 31;

    __shared__ int sN[CHUNK];

    int s = g_off[r];
    int deg = g_off[r + 1] - s;

    float qv = g_qkv[(size_t)r * 768 + warp * 96 + lane];
    float m = -INFINITY, l = 0.f, acc = 0.f;

    for (int base = 0; base < deg; base += CHUNK) {
        int cnt = min(CHUNK, deg - base);
        __syncthreads();
        for (int i = tid; i < cnt; i += 256) sN[i] = g_nbr[s + base + i];
        __syncthreads();
        for (int i = 0; i < cnt; i++) {
            int c = sN[i];
            const float* base_c = &g_qkv[(size_t)c * 768 + warp * 96 + lane];
            float kv = base_c[32];
            float p = qv * kv;
            p += __shfl_xor_sync(0xffffffffu, p, 16);
            p += __shfl_xor_sync(0xffffffffu, p, 8);
            p += __shfl_xor_sync(0xffffffffu, p, 4);
            p += __shfl_xor_sync(0xffffffffu, p, 2);
            p += __shfl_xor_sync(0xffffffffu, p, 1);
            float alpha = p * SCALE;
            float nm = fmaxf(m, alpha);
            float w = __expf(alpha - nm);
            float corr = __expf(m - nm);   // 0 when m == -inf
            float vv = base_c[64];
            l = l * corr + w;
            acc = acc * corr + w * vv;
            m = nm;
        }
    }
    float o = (l > 0.f) ? (acc / l) : 0.f;
    g_attn[(size_t)r * DD + warp * HDIM + lane] = o;
}

// ---------------- residual add + LayerNorm (warp per row) ------------------
__global__ __launch_bounds__(256) void add_ln_kernel(
    const float* __restrict__ a, const float* __restrict__ b,
    const float* __restrict__ gamma, const float* __restrict__ beta,
    float* __restrict__ out)
{
    int row = blockIdx.x * 8 + (threadIdx.x >> 5);
    int lane = threadIdx.x & 31;
    if (row >= NN) return;
    const float* ar = a + (size_t)row * DD;
    const float* br = b + (size_t)row * DD;

    float v[8];
    float s = 0.f;
    #pragma unroll
    for (int i = 0; i < 8; i++) {
        int c = lane + i * 32;
        v[i] = ar[c] + br[c];
        s += v[i];
    }
    #pragma unroll
    for (int d = 16; d > 0; d >>= 1) s += __shfl_xor_sync(0xffffffffu, s, d);
    float mean = s * (1.f / 256.f);

    float vs = 0.f;
    #pragma unroll
    for (int i = 0; i < 8; i++) {
        float dv = v[i] - mean;
        vs += dv * dv;
    }
    #pragma unroll
    for (int d = 16; d > 0; d >>= 1) vs += __shfl_xor_sync(0xffffffffu, vs, d);
    float rstd = rsqrtf(vs * (1.f / 256.f) + EPSL);

    #pragma unroll
    for (int i = 0; i < 8; i++) {
        int c = lane + i * 32;
        out[(size_t)row * DD + c] = (v[i] - mean) * rstd * gamma[c] + beta[c];
    }
}

// ---------------- launcher --------------------------------------------------
extern "C" void kernel_launch(void* const* d_in, const int* in_sizes, int n_in,
                              void* d_out, int out_size)
{
    const float* x      = (const float*)d_in[0];
    const int*   ei     = (const int*)d_in[1];
    const float* w_qkv  = (const float*)d_in[2];
    const float* b_qkv  = (const float*)d_in[3];
    const float* ln1_g  = (const float*)d_in[4];
    const float* ln1_b  = (const float*)d_in[5];
    const float* ln2_g  = (const float*)d_in[6];
    const float* ln2_b  = (const float*)d_in[7];
    const float* w1     = (const float*)d_in[8];
    const float* b1     = (const float*)d_in[9];
    const float* w2     = (const float*)d_in[10];
    const float* b2     = (const float*)d_in[11];
    float* out = (float*)d_out;

    const int* rows = ei;
    const int* cols = ei + EE;

    float *p_qkv, *p_attn, *p_x1, *p_hidden, *p_ffn;
    cudaGetSymbolAddress((void**)&p_qkv, g_qkv);
    cudaGetSymbolAddress((void**)&p_attn, g_attn);
    cudaGetSymbolAddress((void**)&p_x1, g_x1);
    cudaGetSymbolAddress((void**)&p_hidden, g_hidden);
    cudaGetSymbolAddress((void**)&p_ffn, g_ffn);

    // 1) CSR build
    zero_counts_kernel<<<(NN + 255) / 256, 256>>>();
    hist_kernel<<<(EE + 255) / 256, 256>>>(rows);
    scan_kernel<<<1, 1024>>>();
    scatter_kernel<<<(EE + 255) / 256, 256>>>(rows, cols);

    // 2) QKV projection: [N,256] @ [256,768]
    {
        dim3 grid(768 / BN, (NN + BM - 1) / BM);
        sgemm_kernel<false><<<grid, 256>>>(x, w_qkv, b_qkv, p_qkv, NN, 768, 256);
    }

    // 3) attention (per-node online softmax, atomic-free aggregation)
    attn_kernel<<<NN, 256>>>();

    // 4) x1 = LN(x + attn)
    add_ln_kernel<<<(NN + 7) / 8, 256>>>(x, p_attn, ln1_g, ln1_b, p_x1);

    // 5) hidden = relu(x1 @ w1 + b1): [N,256]@[256,1024]
    {
        dim3 grid(FF / BN, (NN + BM - 1) / BM);
        sgemm_kernel<true><<<grid, 256>>>(p_x1, w1, b1, p_hidden, NN, FF, 256);
    }

    // 6) ffn = hidden @ w2 + b2: [N,1024]@[1024,256]
    {
        dim3 grid(DD / BN, (NN + BM - 1) / BM);
        sgemm_kernel<false><<<grid, 256>>>(p_hidden, w2, b2, p_ffn, NN, DD, FF);
    }

    // 7) out = LN(x1 + ffn)
    add_ln_kernel<<<(NN + 7) / 8, 256>>>(p_x1, p_ffn, ln2_g, ln2_b, out);
}

// round 3
// speedup vs baseline: 1.8421x; 1.8421x over previous
#include <cuda_runtime.h>
#include <math.h>
#include <stdint.h>

#define NN 50000
#define EE 800000
#define DD 256
#define HH 8
#define HDIM 32
#define FF 1024
#define SCALE 0.0625f   // 256^-0.5
#define EPSL 1e-5f

// ---------------- scratch (device globals; no allocation allowed) ----------
__device__ float g_qkv[(size_t)NN * 768];     // per node: H heads x (q|k|v) 96 floats
__device__ float g_attn[(size_t)NN * DD];
__device__ float g_x1[(size_t)NN * DD];
__device__ float g_hidden[(size_t)NN * FF];
__device__ float g_ffn[(size_t)NN * DD];
__device__ int   g_deg[NN];
__device__ int   g_off[NN + 1];
__device__ int   g_cursor[NN];
__device__ int   g_nbr[EE];

// ---------------- CSR construction -----------------------------------------
__global__ void zero_counts_kernel() {
    int i = blockIdx.x * blockDim.x + threadIdx.x;
    if (i < NN) { g_deg[i] = 0; g_cursor[i] = 0; }
}

__global__ void hist_kernel(const int* __restrict__ rows) {
    int e = blockIdx.x * blockDim.x + threadIdx.x;
    if (e < EE) atomicAdd(&g_deg[rows[e]], 1);
}

__global__ void scan_kernel() {
    __shared__ int sh[1024];
    __shared__ int carry;
    int t = threadIdx.x;
    if (t == 0) { carry = 0; g_off[0] = 0; }
    __syncthreads();
    for (int base = 0; base < NN; base += 1024) {
        int i = base + t;
        int v = (i < NN) ? g_deg[i] : 0;
        sh[t] = v;
        __syncthreads();
        #pragma unroll
        for (int d = 1; d < 1024; d <<= 1) {
            int tv = (t >= d) ? sh[t - d] : 0;
            __syncthreads();
            sh[t] += tv;
            __syncthreads();
        }
        if (i < NN) g_off[i + 1] = carry + sh[t];
        __syncthreads();
        if (t == 0) carry += sh[1023];
        __syncthreads();
    }
}

__global__ void scatter_kernel(const int* __restrict__ rows, const int* __restrict__ cols) {
    int e = blockIdx.x * blockDim.x + threadIdx.x;
    if (e < EE) {
        int r = rows[e];
        int pos = g_off[r] + atomicAdd(&g_cursor[r], 1);
        g_nbr[pos] = cols[e];
    }
}

// ---------------- TF32 tensor-core GEMM ------------------------------------
// C[M,N] = A[M,K] @ B[K,N] + bias (optional ReLU).
// Block tile 128x128x32, 256 threads (8 warps), warp tile 64x32.
// mma.sync.aligned.m16n8k8 tf32.
#define BM 128
#define BN 128
#define BK 32

__device__ __forceinline__ uint32_t f2tf32(float f) {
    uint32_t u;
    asm("cvt.rna.tf32.f32 %0, %1;" : "=r"(u) : "f"(f));
    return u;
}

__device__ __forceinline__ void mma_tf32(float c[4], const uint32_t a[4], const uint32_t b[2]) {
    asm volatile(
        "mma.sync.aligned.m16n8k8.row.col.f32.tf32.tf32.f32 "
        "{%0,%1,%2,%3}, {%4,%5,%6,%7}, {%8,%9}, {%0,%1,%2,%3};\n"
        : "+f"(c[0]), "+f"(c[1]), "+f"(c[2]), "+f"(c[3])
        : "r"(a[0]), "r"(a[1]), "r"(a[2]), "r"(a[3]), "r"(b[0]), "r"(b[1]));
}

template <bool RELU>
__global__ __launch_bounds__(256, 2) void gemm_tf32_kernel(
    const float* __restrict__ A, const float* __restrict__ B,
    const float* __restrict__ bias, float* __restrict__ C,
    int M, int N, int K)
{
    // As stored transposed: As[k][m]; Bs row-major: Bs[k][n]. Padded stride.
    __shared__ uint32_t As[BK][BM + 4];
    __shared__ uint32_t Bs[BK][BN + 4];

    int tid  = threadIdx.x;
    int lane = tid & 31;
    int warp = tid >> 5;
    int warp_m = warp >> 2;      // 0..1  -> 64-row slab
    int warp_n = warp & 3;       // 0..3  -> 32-col slab
    int g   = lane >> 2;         // groupID 0..7
    int tig = lane & 3;          // thread-in-group 0..3

    int brow = blockIdx.y * BM;
    int bcol = blockIdx.x * BN;

    float acc[4][4][4];
    #pragma unroll
    for (int i = 0; i < 4; i++)
        #pragma unroll
        for (int j = 0; j < 4; j++)
            #pragma unroll
            for (int r = 0; r < 4; r++) acc[i][j][r] = 0.f;

    int mb = warp_m * 64;
    int nb = warp_n * 32;

    for (int k0 = 0; k0 < K; k0 += BK) {
        // ---- load A tile (128x32), cvt to tf32, store transposed ----
        #pragma unroll
        for (int i = 0; i < 4; i++) {
            int idx  = tid + i * 256;           // 0..1023
            int arow = idx >> 3;                // 0..127
            int ac4  = (idx & 7) * 4;           // 0..28
            int gr = brow + arow;
            float4 a4 = (gr < M)
                ? *reinterpret_cast<const float4*>(&A[(size_t)gr * K + k0 + ac4])
                : make_float4(0.f, 0.f, 0.f, 0.f);
            As[ac4 + 0][arow] = f2tf32(a4.x);
            As[ac4 + 1][arow] = f2tf32(a4.y);
            As[ac4 + 2][arow] = f2tf32(a4.z);
            As[ac4 + 3][arow] = f2tf32(a4.w);
        }
        // ---- load B tile (32x128), cvt to tf32 ----
        #pragma unroll
        for (int i = 0; i < 4; i++) {
            int idx  = tid + i * 256;
            int brw  = idx >> 5;                // 0..31
            int bc4  = (idx & 31) * 4;          // 0..124
            float4 b4 = *reinterpret_cast<const float4*>(&B[(size_t)(k0 + brw) * N + bcol + bc4]);
            Bs[brw][bc4 + 0] = f2tf32(b4.x);
            Bs[brw][bc4 + 1] = f2tf32(b4.y);
            Bs[brw][bc4 + 2] = f2tf32(b4.z);
            Bs[brw][bc4 + 3] = f2tf32(b4.w);
        }
        __syncthreads();

        #pragma unroll
        for (int kk = 0; kk < BK; kk += 8) {
            uint32_t afr[4][4];
            uint32_t bfr[4][2];
            #pragma unroll
            for (int i = 0; i < 4; i++) {
                int m0 = mb + i * 16;
                afr[i][0] = As[kk + tig    ][m0 + g];
                afr[i][1] = As[kk + tig    ][m0 + g + 8];
                afr[i][2] = As[kk + tig + 4][m0 + g];
                afr[i][3] = As[kk + tig + 4][m0 + g + 8];
            }
            #pragma unroll
            for (int j = 0; j < 4; j++) {
                int n0 = nb + j * 8;
                bfr[j][0] = Bs[kk + tig    ][n0 + g];
                bfr[j][1] = Bs[kk + tig + 4][n0 + g];
            }
            #pragma unroll
            for (int i = 0; i < 4; i++)
                #pragma unroll
                for (int j = 0; j < 4; j++)
                    mma_tf32(acc[i][j], afr[i], bfr[j]);
        }
        __syncthreads();
    }

    // ---- epilogue: bias (+relu), store ----
    #pragma unroll
    for (int i = 0; i < 4; i++) {
        #pragma unroll
        for (int half = 0; half < 2; half++) {
            int gr = brow + mb + i * 16 + g + half * 8;
            if (gr < M) {
                #pragma unroll
                for (int j = 0; j < 4; j++) {
                    int gc = bcol + nb + j * 8 + 2 * tig;
                    float c0 = acc[i][j][half * 2 + 0] + bias[gc];
                    float c1 = acc[i][j][half * 2 + 1] + bias[gc + 1];
                    if (RELU) { c0 = fmaxf(c0, 0.f); c1 = fmaxf(c1, 0.f); }
                    float2 o = make_float2(c0, c1);
                    *reinterpret_cast<float2*>(&C[(size_t)gr * N + gc]) = o;
                }
            }
        }
    }
}

// ---------------- fused per-node attention (online softmax) ----------------
// One block per node (256 threads = 8 warps); warp h handles head h;
// lane d holds dimension d of that head.
// qkv layout per node: head h occupies [h*96, h*96+96): q|k|v of 32 each.
#define CHUNK 256

__global__ __launch_bounds__(256) void attn_kernel() {
    int r = blockIdx.x;
    int tid = threadIdx.x;
    int warp = tid >> 5;
    int lane = tid & 31;

    __shared__ int sN[CHUNK];

    int s = g_off[r];
    int deg = g_off[r + 1] - s;

    float qv = g_qkv[(size_t)r * 768 + warp * 96 + lane];
    float m = -INFINITY, l = 0.f, acc = 0.f;

    for (int base = 0; base < deg; base += CHUNK) {
        int cnt = min(CHUNK, deg - base);
        __syncthreads();
        for (int i = tid; i < cnt; i += 256) sN[i] = g_nbr[s + base + i];
        __syncthreads();
        int i = 0;
        for (; i + 1 < cnt; i += 2) {
            int c0 = sN[i], c1 = sN[i + 1];
            const float* p0 = &g_qkv[(size_t)c0 * 768 + warp * 96 + lane];
            const float* p1 = &g_qkv[(size_t)c1 * 768 + warp * 96 + lane];
            float k0 = p0[32], k1 = p1[32];
            float v0 = p0[64], v1 = p1[64];
            float d0 = qv * k0, d1 = qv * k1;
            #pragma unroll
            for (int sh = 16; sh > 0; sh >>= 1) {
                d0 += __shfl_xor_sync(0xffffffffu, d0, sh);
                d1 += __shfl_xor_sync(0xffffffffu, d1, sh);
            }
            float a0 = d0 * SCALE, a1 = d1 * SCALE;
            float nm = fmaxf(m, fmaxf(a0, a1));
            float w0 = __expf(a0 - nm);
            float w1 = __expf(a1 - nm);
            float corr = __expf(m - nm);   // 0 when m == -inf
            l   = l * corr + w0 + w1;
            acc = acc * corr + w0 * v0 + w1 * v1;
            m = nm;
        }
        if (i < cnt) {
            int c = sN[i];
            const float* p = &g_qkv[(size_t)c * 768 + warp * 96 + lane];
            float kv = p[32];
            float vv = p[64];
            float d = qv * kv;
            #pragma unroll
            for (int sh = 16; sh > 0; sh >>= 1)
                d += __shfl_xor_sync(0xffffffffu, d, sh);
            float a = d * SCALE;
            float nm = fmaxf(m, a);
            float w = __expf(a - nm);
            float corr = __expf(m - nm);
            l   = l * corr + w;
            acc = acc * corr + w * vv;
            m = nm;
        }
    }
    float o = (l > 0.f) ? (acc / l) : 0.f;
    g_attn[(size_t)r * DD + warp * HDIM + lane] = o;
}

// ---------------- residual add + LayerNorm (warp per row) ------------------
__global__ __launch_bounds__(256) void add_ln_kernel(
    const float* __restrict__ a, const float* __restrict__ b,
    const float* __restrict__ gamma, const float* __restrict__ beta,
    float* __restrict__ out)
{
    int row = blockIdx.x * 8 + (threadIdx.x >> 5);
    int lane = threadIdx.x & 31;
    if (row >= NN) return;
    const float* ar = a + (size_t)row * DD;
    const float* br = b + (size_t)row * DD;

    float v[8];
    float s = 0.f;
    #pragma unroll
    for (int i = 0; i < 8; i++) {
        int c = lane + i * 32;
        v[i] = ar[c] + br[c];
        s += v[i];
    }
    #pragma unroll
    for (int d = 16; d > 0; d >>= 1) s += __shfl_xor_sync(0xffffffffu, s, d);
    float mean = s * (1.f / 256.f);

    float vs = 0.f;
    #pragma unroll
    for (int i = 0; i < 8; i++) {
        float dv = v[i] - mean;
        vs += dv * dv;
    }
    #pragma unroll
    for (int d = 16; d > 0; d >>= 1) vs += __shfl_xor_sync(0xffffffffu, vs, d);
    float rstd = rsqrtf(vs * (1.f / 256.f) + EPSL);

    #pragma unroll
    for (int i = 0; i < 8; i++) {
        int c = lane + i * 32;
        out[(size_t)row * DD + c] = (v[i] - mean) * rstd * gamma[c] + beta[c];
    }
}

// ---------------- launcher --------------------------------------------------
extern "C" void kernel_launch(void* const* d_in, const int* in_sizes, int n_in,
                              void* d_out, int out_size)
{
    const float* x      = (const float*)d_in[0];
    const int*   ei     = (const int*)d_in[1];
    const float* w_qkv  = (const float*)d_in[2];
    const float* b_qkv  = (const float*)d_in[3];
    const float* ln1_g  = (const float*)d_in[4];
    const float* ln1_b  = (const float*)d_in[5];
    const float* ln2_g  = (const float*)d_in[6];
    const float* ln2_b  = (const float*)d_in[7];
    const float* w1     = (const float*)d_in[8];
    const float* b1     = (const float*)d_in[9];
    const float* w2     = (const float*)d_in[10];
    const float* b2     = (const float*)d_in[11];
    float* out = (float*)d_out;

    const int* rows = ei;
    const int* cols = ei + EE;

    float *p_qkv, *p_attn, *p_x1, *p_hidden, *p_ffn;
    cudaGetSymbolAddress((void**)&p_qkv, g_qkv);
    cudaGetSymbolAddress((void**)&p_attn, g_attn);
    cudaGetSymbolAddress((void**)&p_x1, g_x1);
    cudaGetSymbolAddress((void**)&p_hidden, g_hidden);
    cudaGetSymbolAddress((void**)&p_ffn, g_ffn);

    // 1) CSR build
    zero_counts_kernel<<<(NN + 255) / 256, 256>>>();
    hist_kernel<<<(EE + 255) / 256, 256>>>(rows);
    scan_kernel<<<1, 1024>>>();
    scatter_kernel<<<(EE + 255) / 256, 256>>>(rows, cols);

    // 2) QKV projection: [N,256] @ [256,768]
    {
        dim3 grid(768 / BN, (NN + BM - 1) / BM);
        gemm_tf32_kernel<false><<<grid, 256>>>(x, w_qkv, b_qkv, p_qkv, NN, 768, 256);
    }

    // 3) attention (per-node online softmax, atomic-free aggregation)
    attn_kernel<<<NN, 256>>>();

    // 4) x1 = LN(x + attn)
    add_ln_kernel<<<(NN + 7) / 8, 256>>>(x, p_attn, ln1_g, ln1_b, p_x1);

    // 5) hidden = relu(x1 @ w1 + b1): [N,256]@[256,1024]
    {
        dim3 grid(FF / BN, (NN + BM - 1) / BM);
        gemm_tf32_kernel<true><<<grid, 256>>>(p_x1, w1, b1, p_hidden, NN, FF, 256);
    }

    // 6) ffn = hidden @ w2 + b2: [N,1024]@[1024,256]
    {
        dim3 grid(DD / BN, (NN + BM - 1) / BM);
        gemm_tf32_kernel<false><<<grid, 256>>>(p_hidden, w2, b2, p_ffn, NN, DD, FF);
    }

    // 7) out = LN(x1 + ffn)
    add_ln_kernel<<<(NN + 7) / 8, 256>>>(p_x1, p_ffn, ln2_g, ln2_b, out);
}

// round 4
// speedup vs baseline: 2.2597x; 1.2267x over previous
#include <cuda_runtime.h>
#include <cuda_bf16.h>
#include <math.h>
#include <stdint.h>

#define NN 50000
#define EE 800000
#define DD 256
#define HH 8
#define HDIM 32
#define FF 1024
#define SCALE 0.0625f   // 256^-0.5
#define EPSL 1e-5f

// ---------------- scratch (device globals; no allocation allowed) ----------
__device__ float g_qkv[(size_t)NN * 768];     // per node: H heads x (q|k|v) 96 floats
__device__ __nv_bfloat16 g_kv[(size_t)NN * 512]; // per node: H heads x (k32|v32) bf16
__device__ float g_attn[(size_t)NN * DD];
__device__ float g_x1[(size_t)NN * DD];
__device__ float g_hidden[(size_t)NN * FF];
__device__ float g_ffn[(size_t)NN * DD];
__device__ int   g_deg[NN];
__device__ int   g_off[NN + 1];
__device__ int   g_cursor[NN];
__device__ int   g_nbr[EE];

// ---------------- CSR construction -----------------------------------------
__global__ void zero_counts_kernel() {
    int i = blockIdx.x * blockDim.x + threadIdx.x;
    if (i < NN) { g_deg[i] = 0; g_cursor[i] = 0; }
}

__global__ void hist_kernel(const int* __restrict__ rows) {
    int e = blockIdx.x * blockDim.x + threadIdx.x;
    if (e < EE) atomicAdd(&g_deg[rows[e]], 1);
}

__global__ void scan_kernel() {
    __shared__ int sh[1024];
    __shared__ int carry;
    int t = threadIdx.x;
    if (t == 0) { carry = 0; g_off[0] = 0; }
    __syncthreads();
    for (int base = 0; base < NN; base += 1024) {
        int i = base + t;
        int v = (i < NN) ? g_deg[i] : 0;
        sh[t] = v;
        __syncthreads();
        #pragma unroll
        for (int d = 1; d < 1024; d <<= 1) {
            int tv = (t >= d) ? sh[t - d] : 0;
            __syncthreads();
            sh[t] += tv;
            __syncthreads();
        }
        if (i < NN) g_off[i + 1] = carry + sh[t];
        __syncthreads();
        if (t == 0) carry += sh[1023];
        __syncthreads();
    }
}

__global__ void scatter_kernel(const int* __restrict__ rows, const int* __restrict__ cols) {
    int e = blockIdx.x * blockDim.x + threadIdx.x;
    if (e < EE) {
        int r = rows[e];
        int pos = g_off[r] + atomicAdd(&g_cursor[r], 1);
        g_nbr[pos] = cols[e];
    }
}

// ---------------- pack k/v to bf16 for the attention gather ----------------
// g_kv[node][head][0..31] = k, [head][32..63] = v.
// src col for (head, pos) = head*96 + 32 + pos   (pos in [0,64))
__global__ __launch_bounds__(256) void pack_kv_kernel() {
    size_t idx = (size_t)blockIdx.x * blockDim.x + threadIdx.x;
    size_t total = (size_t)NN * 512;
    if (idx >= total) return;
    size_t node = idx >> 9;
    int rem = (int)(idx & 511);
    int head = rem >> 6;
    int pos = rem & 63;
    float v = g_qkv[node * 768 + head * 96 + 32 + pos];
    g_kv[idx] = __float2bfloat16(v);
}

// ---------------- TF32 tensor-core GEMM (cp.async double-buffered) ---------
// C[M,N] = A[M,K] @ B[K,N] + bias (optional ReLU).
// Block tile 128x128x32, 256 threads (8 warps), warp tile 64x32.
// Raw fp32 bits fed to tf32 mma (hardware truncation).
#define BM 128
#define BN 128
#define BK 32
#define ASTRIDE 36    // (BK+4) words; 4g+tig unique banks, 16B-aligned rows
#define BSTRIDE 136   // (BN+8) words; 8tig+g unique banks, 16B-aligned rows

__device__ __forceinline__ void cp_async16(uint32_t smem_addr, const void* gptr, int src_bytes) {
    asm volatile("cp.async.cg.shared.global [%0], [%1], 16, %2;\n"
                 :: "r"(smem_addr), "l"(gptr), "r"(src_bytes));
}
__device__ __forceinline__ void cp_commit() {
    asm volatile("cp.async.commit_group;\n");
}
template <int NREM>
__device__ __forceinline__ void cp_wait() {
    asm volatile("cp.async.wait_group %0;\n" :: "n"(NREM));
}

__device__ __forceinline__ void mma_tf32(float c[4], const uint32_t a[4], const uint32_t b[2]) {
    asm volatile(
        "mma.sync.aligned.m16n8k8.row.col.f32.tf32.tf32.f32 "
        "{%0,%1,%2,%3}, {%4,%5,%6,%7}, {%8,%9}, {%0,%1,%2,%3};\n"
        : "+f"(c[0]), "+f"(c[1]), "+f"(c[2]), "+f"(c[3])
        : "r"(a[0]), "r"(a[1]), "r"(a[2]), "r"(a[3]), "r"(b[0]), "r"(b[1]));
}

template <bool RELU>
__global__ __launch_bounds__(256, 2) void gemm_tf32_kernel(
    const float* __restrict__ A, const float* __restrict__ B,
    const float* __restrict__ bias, float* __restrict__ C,
    int M, int N, int K)
{
    // A tile row-major As[m][k] (stride ASTRIDE), B tile Bs[k][n] (stride BSTRIDE)
    __shared__ uint32_t As[2][BM * ASTRIDE];
    __shared__ uint32_t Bs[2][BK * BSTRIDE];

    int tid  = threadIdx.x;
    int lane = tid & 31;
    int warp = tid >> 5;
    int warp_m = warp >> 2;      // 0..1
    int warp_n = warp & 3;       // 0..3
    int g   = lane >> 2;         // 0..7
    int tig = lane & 3;          // 0..3

    int brow = blockIdx.y * BM;
    int bcol = blockIdx.x * BN;
    int mb = warp_m * 64;
    int nb = warp_n * 32;

    // per-thread cp.async source/dest coordinates
    int aRow = tid >> 1;                 // with 4 chunks: rows tid>>1 per half... (see below)
    // A tile: 128 rows x 8 chunks (16B) = 1024 chunks; thread does 4.
    // chunk id = tid + i*256 -> row = id>>3, c4 = (id&7)*4 (words)
    // B tile: 32 rows x 32 chunks = 1024 chunks; id -> row = id>>5, c4 = (id&31)*4
    (void)aRow;

    uint32_t as_base = (uint32_t)__cvta_generic_to_shared(&As[0][0]);
    uint32_t bs_base = (uint32_t)__cvta_generic_to_shared(&Bs[0][0]);

    float acc[4][4][4];
    #pragma unroll
    for (int i = 0; i < 4; i++)
        #pragma unroll
        for (int j = 0; j < 4; j++)
            #pragma unroll
            for (int r = 0; r < 4; r++) acc[i][j][r] = 0.f;

    int nk = K / BK;

    // ---- tile loader ----
    auto load_tiles = [&](int t, int buf) {
        int k0 = t * BK;
        #pragma unroll
        for (int i = 0; i < 4; i++) {
            int id = tid + i * 256;
            int row = id >> 3;
            int c4  = (id & 7) * 4;
            int gr = brow + row;
            const float* src = &A[(size_t)gr * K + k0 + c4];
            uint32_t dst = as_base + (buf * BM * ASTRIDE + row * ASTRIDE + c4) * 4;
            cp_async16(dst, src, (gr < M) ? 16 : 0);
        }
        #pragma unroll
        for (int i = 0; i < 4; i++) {
            int id = tid + i * 256;
            int row = id >> 5;
            int c4  = (id & 31) * 4;
            const float* src = &B[(size_t)(k0 + row) * N + bcol + c4];
            uint32_t dst = bs_base + (buf * BK * BSTRIDE + row * BSTRIDE + c4) * 4;
            cp_async16(dst, src, 16);
        }
        cp_commit();
    };

    load_tiles(0, 0);

    for (int t = 0; t < nk; t++) {
        int buf = t & 1;
        if (t + 1 < nk) {
            load_tiles(t + 1, (t + 1) & 1);
            cp_wait<1>();
        } else {
            cp_wait<0>();
        }
        __syncthreads();

        const uint32_t* Asb = &As[0][0] + buf * BM * ASTRIDE;
        const uint32_t* Bsb = &Bs[0][0] + buf * BK * BSTRIDE;

        #pragma unroll
        for (int kk = 0; kk < BK; kk += 8) {
            uint32_t afr[4][4];
            uint32_t bfr[4][2];
            #pragma unroll
            for (int i = 0; i < 4; i++) {
                int m0 = mb + i * 16;
                afr[i][0] = Asb[(m0 + g    ) * ASTRIDE + kk + tig    ];
                afr[i][1] = Asb[(m0 + g + 8) * ASTRIDE + kk + tig    ];
                afr[i][2] = Asb[(m0 + g    ) * ASTRIDE + kk + tig + 4];
                afr[i][3] = Asb[(m0 + g + 8) * ASTRIDE + kk + tig + 4];
            }
            #pragma unroll
            for (int j = 0; j < 4; j++) {
                int n0 = nb + j * 8;
                bfr[j][0] = Bsb[(kk + tig    ) * BSTRIDE + n0 + g];
                bfr[j][1] = Bsb[(kk + tig + 4) * BSTRIDE + n0 + g];
            }
            #pragma unroll
            for (int i = 0; i < 4; i++)
                #pragma unroll
                for (int j = 0; j < 4; j++)
                    mma_tf32(acc[i][j], afr[i], bfr[j]);
        }
        __syncthreads();
    }

    // ---- epilogue: bias (+relu), store ----
    #pragma unroll
    for (int i = 0; i < 4; i++) {
        #pragma unroll
        for (int half = 0; half < 2; half++) {
            int gr = brow + mb + i * 16 + g + half * 8;
            if (gr < M) {
                #pragma unroll
                for (int j = 0; j < 4; j++) {
                    int gc = bcol + nb + j * 8 + 2 * tig;
                    float c0 = acc[i][j][half * 2 + 0] + bias[gc];
                    float c1 = acc[i][j][half * 2 + 1] + bias[gc + 1];
                    if (RELU) { c0 = fmaxf(c0, 0.f); c1 = fmaxf(c1, 0.f); }
                    float2 o = make_float2(c0, c1);
                    *reinterpret_cast<float2*>(&C[(size_t)gr * N + gc]) = o;
                }
            }
        }
    }
}

// ---------------- fused per-node attention (online softmax) ----------------
// One block per node (256 threads = 8 warps); warp h handles head h;
// lane d holds dimension d of that head. k/v gathered from bf16 g_kv.
#define CHUNK 256

__global__ __launch_bounds__(256) void attn_kernel() {
    int r = blockIdx.x;
    int tid = threadIdx.x;
    int warp = tid >> 5;
    int lane = tid & 31;

    __shared__ int sN[CHUNK];

    int s = g_off[r];
    int deg = g_off[r + 1] - s;

    float qv = g_qkv[(size_t)r * 768 + warp * 96 + lane];
    float m = -INFINITY, l = 0.f, acc = 0.f;

    for (int base = 0; base < deg; base += CHUNK) {
        int cnt = min(CHUNK, deg - base);
        __syncthreads();
        for (int i = tid; i < cnt; i += 256) sN[i] = g_nbr[s + base + i];
        __syncthreads();
        int i = 0;
        for (; i + 1 < cnt; i += 2) {
            int c0 = sN[i], c1 = sN[i + 1];
            const __nv_bfloat16* p0 = &g_kv[((size_t)c0 * 8 + warp) * 64 + lane];
            const __nv_bfloat16* p1 = &g_kv[((size_t)c1 * 8 + warp) * 64 + lane];
            float k0 = __bfloat162float(p0[0]);
            float k1 = __bfloat162float(p1[0]);
            float v0 = __bfloat162float(p0[32]);
            float v1 = __bfloat162float(p1[32]);
            float d0 = qv * k0, d1 = qv * k1;
            #pragma unroll
            for (int sh = 16; sh > 0; sh >>= 1) {
                d0 += __shfl_xor_sync(0xffffffffu, d0, sh);
                d1 += __shfl_xor_sync(0xffffffffu, d1, sh);
            }
            float a0 = d0 * SCALE, a1 = d1 * SCALE;
            float nm = fmaxf(m, fmaxf(a0, a1));
            float w0 = __expf(a0 - nm);
            float w1 = __expf(a1 - nm);
            float corr = __expf(m - nm);   // 0 when m == -inf
            l   = l * corr + w0 + w1;
            acc = acc * corr + w0 * v0 + w1 * v1;
            m = nm;
        }
        if (i < cnt) {
            int c = sN[i];
            const __nv_bfloat16* p = &g_kv[((size_t)c * 8 + warp) * 64 + lane];
            float kv = __bfloat162float(p[0]);
            float vv = __bfloat162float(p[32]);
            float d = qv * kv;
            #pragma unroll
            for (int sh = 16; sh > 0; sh >>= 1)
                d += __shfl_xor_sync(0xffffffffu, d, sh);
            float a = d * SCALE;
            float nm = fmaxf(m, a);
            float w = __expf(a - nm);
            float corr = __expf(m - nm);
            l   = l * corr + w;
            acc = acc * corr + w * vv;
            m = nm;
        }
    }
    float o = (l > 0.f) ? (acc / l) : 0.f;
    g_attn[(size_t)r * DD + warp * HDIM + lane] = o;
}

// ---------------- residual add + LayerNorm (warp per row) ------------------
__global__ __launch_bounds__(256) void add_ln_kernel(
    const float* __restrict__ a, const float* __restrict__ b,
    const float* __restrict__ gamma, const float* __restrict__ beta,
    float* __restrict__ out)
{
    int row = blockIdx.x * 8 + (threadIdx.x >> 5);
    int lane = threadIdx.x & 31;
    if (row >= NN) return;
    const float* ar = a + (size_t)row * DD;
    const float* br = b + (size_t)row * DD;

    float v[8];
    float s = 0.f;
    #pragma unroll
    for (int i = 0; i < 8; i++) {
        int c = lane + i * 32;
        v[i] = ar[c] + br[c];
        s += v[i];
    }
    #pragma unroll
    for (int d = 16; d > 0; d >>= 1) s += __shfl_xor_sync(0xffffffffu, s, d);
    float mean = s * (1.f / 256.f);

    float vs = 0.f;
    #pragma unroll
    for (int i = 0; i < 8; i++) {
        float dv = v[i] - mean;
        vs += dv * dv;
    }
    #pragma unroll
    for (int d = 16; d > 0; d >>= 1) vs += __shfl_xor_sync(0xffffffffu, vs, d);
    float rstd = rsqrtf(vs * (1.f / 256.f) + EPSL);

    #pragma unroll
    for (int i = 0; i < 8; i++) {
        int c = lane + i * 32;
        out[(size_t)row * DD + c] = (v[i] - mean) * rstd * gamma[c] + beta[c];
    }
}

// ---------------- launcher --------------------------------------------------
extern "C" void kernel_launch(void* const* d_in, const int* in_sizes, int n_in,
                              void* d_out, int out_size)
{
    const float* x      = (const float*)d_in[0];
    const int*   ei     = (const int*)d_in[1];
    const float* w_qkv  = (const float*)d_in[2];
    const float* b_qkv  = (const float*)d_in[3];
    const float* ln1_g  = (const float*)d_in[4];
    const float* ln1_b  = (const float*)d_in[5];
    const float* ln2_g  = (const float*)d_in[6];
    const float* ln2_b  = (const float*)d_in[7];
    const float* w1     = (const float*)d_in[8];
    const float* b1     = (const float*)d_in[9];
    const float* w2     = (const float*)d_in[10];
    const float* b2     = (const float*)d_in[11];
    float* out = (float*)d_out;

    const int* rows = ei;
    const int* cols = ei + EE;

    float *p_qkv, *p_attn, *p_x1, *p_hidden, *p_ffn;
    cudaGetSymbolAddress((void**)&p_qkv, g_qkv);
    cudaGetSymbolAddress((void**)&p_attn, g_attn);
    cudaGetSymbolAddress((void**)&p_x1, g_x1);
    cudaGetSymbolAddress((void**)&p_hidden, g_hidden);
    cudaGetSymbolAddress((void**)&p_ffn, g_ffn);

    // 1) CSR build
    zero_counts_kernel<<<(NN + 255) / 256, 256>>>();
    hist_kernel<<<(EE + 255) / 256, 256>>>(rows);
    scan_kernel<<<1, 1024>>>();
    scatter_kernel<<<(EE + 255) / 256, 256>>>(rows, cols);

    // 2) QKV projection: [N,256] @ [256,768]
    {
        dim3 grid(768 / BN, (NN + BM - 1) / BM);
        gemm_tf32_kernel<false><<<grid, 256>>>(x, w_qkv, b_qkv, p_qkv, NN, 768, 256);
    }

    // 2b) pack k/v to bf16
    {
        size_t total = (size_t)NN * 512;
        pack_kv_kernel<<<(unsigned)((total + 255) / 256), 256>>>();
    }

    // 3) attention
    attn_kernel<<<NN, 256>>>();

    // 4) x1 = LN(x + attn)
    add_ln_kernel<<<(NN + 7) / 8, 256>>>(x, p_attn, ln1_g, ln1_b, p_x1);

    // 5) hidden = relu(x1 @ w1 + b1)
    {
        dim3 grid(FF / BN, (NN + BM - 1) / BM);
        gemm_tf32_kernel<true><<<grid, 256>>>(p_x1, w1, b1, p_hidden, NN, FF, 256);
    }

    // 6) ffn = hidden @ w2 + b2
    {
        dim3 grid(DD / BN, (NN + BM - 1) / BM);
        gemm_tf32_kernel<false><<<grid, 256>>>(p_hidden, w2, b2, p_ffn, NN, DD, FF);
    }

    // 7) out = LN(x1 + ffn)
    add_ln_kernel<<<(NN + 7) / 8, 256>>>(p_x1, p_ffn, ln2_g, ln2_b, out);
}